// round 6
// baseline (speedup 1.0000x reference)
#include <cuda_runtime.h>
#include <math.h>
#include <stdint.h>

#define HID 128
#define NMAX 50000
#define EMAX 500000
#define NRBF 20
#define PI_OVER_CUT 0.5235987755982988f   // pi / 6
#define CUTOFF 6.0f

typedef unsigned long long u64;

// ---------------- scratch (device globals; no runtime allocation) ----------------
__device__ float g_ns[NMAX * HID];
__device__ float g_nv[NMAX * 3 * HID];
__device__ float g_nvold[NMAX * 3 * HID];
__device__ float g_tmpH[NMAX * HID];
__device__ float g_smsg[NMAX * 3 * HID];
__device__ float g_Uv[NMAX * 3 * HID];
__device__ float g_Vv[NMAX * 3 * HID];
__device__ float g_Vn[NMAX * HID];
__device__ float g_inner[NMAX * HID];
__device__ float g_abuf[NMAX * 3 * HID];

__device__ int   g_act_r[EMAX];
__device__ int   g_act_c[EMAX];
__device__ float g_act_unit[EMAX * 3];
__device__ float g_act_rbf[EMAX * NRBF];
__device__ float g_act_fcut[EMAX];
__device__ int   g_nact;

__device__ __forceinline__ float silu_f(float x) {
    return x / (1.0f + __expf(-x));
}

// packed f32x2 helpers (sm_100+; SASS FFMA2 — ptxas never emits this from C++)
__device__ __forceinline__ u64 fma2(u64 a, u64 b, u64 c) {
    u64 d;
    asm("fma.rn.f32x2 %0, %1, %2, %3;" : "=l"(d) : "l"(a), "l"(b), "l"(c));
    return d;
}
__device__ __forceinline__ u64 dup2(float x) {
    u64 d;
    asm("mov.b64 %0, {%1, %1};" : "=l"(d) : "f"(x));
    return d;
}
__device__ __forceinline__ void unpack2(u64 v, float& lo, float& hi) {
    asm("mov.b64 {%0, %1}, %2;" : "=f"(lo), "=f"(hi) : "l"(v));
}

// ---------------- reset ----------------
__global__ void reset_kernel() { g_nact = 0; }

// ---------------- edge geometry + compaction ----------------
__global__ void edge_geom_kernel(const float* __restrict__ pos,
                                 const float* __restrict__ cell,
                                 const int* __restrict__ ei,
                                 const int* __restrict__ offs,
                                 float* __restrict__ out_dist,
                                 float* __restrict__ out_ei,
                                 int E) {
    int e = blockIdx.x * blockDim.x + threadIdx.x;
    if (e >= E) return;
    int r = ei[e];
    int c = ei[E + e];
    float o0 = (float)offs[e * 3 + 0];
    float o1 = (float)offs[e * 3 + 1];
    float o2 = (float)offs[e * 3 + 2];
    // offsets @ cell  (cell row-major 3x3)
    float ox = o0 * cell[0] + o1 * cell[3] + o2 * cell[6];
    float oy = o0 * cell[1] + o1 * cell[4] + o2 * cell[7];
    float oz = o0 * cell[2] + o1 * cell[5] + o2 * cell[8];
    float dx = pos[r * 3 + 0] - pos[c * 3 + 0] + ox;
    float dy = pos[r * 3 + 1] - pos[c * 3 + 1] + oy;
    float dz = pos[r * 3 + 2] - pos[c * 3 + 2] + oz;
    float dist = sqrtf(dx * dx + dy * dy + dz * dz);
    out_dist[e] = dist;
    out_ei[e] = (float)r;
    out_ei[E + e] = (float)c;

    if (dist < CUTOFF) {
        int idx = atomicAdd(&g_nact, 1);
        g_act_r[idx] = r;
        g_act_c[idx] = c;
        float inv = 1.0f / dist;
        g_act_unit[idx * 3 + 0] = dx * inv;
        g_act_unit[idx * 3 + 1] = dy * inv;
        g_act_unit[idx * 3 + 2] = dz * inv;
        g_act_fcut[idx] = 0.5f * (cosf(dist * PI_OVER_CUT) + 1.0f);
#pragma unroll
        for (int t = 0; t < NRBF; t++) {
            g_act_rbf[idx * NRBF + t] = sinf(dist * (float)(t + 1) * PI_OVER_CUT) * inv;
        }
    }
}

// ---------------- node init: ns = embed[z], nv = nvold = 0 ----------------
__global__ void init_nodes_kernel(const float* __restrict__ embed,
                                  const int* __restrict__ z,
                                  int N) {
    int t = blockIdx.x * blockDim.x + threadIdx.x;
    if (t >= N * HID) return;
    int n = t >> 7;
    int h = t & 127;
    g_ns[t] = embed[z[n] * HID + h];
    int base = n * 3 * HID + h;
    g_nv[base] = 0.0f;
    g_nv[base + HID] = 0.0f;
    g_nv[base + 2 * HID] = 0.0f;
    g_nvold[base] = 0.0f;
    g_nvold[base + HID] = 0.0f;
    g_nvold[base + 2 * HID] = 0.0f;
}

// ================= GEMM core pieces (shared by the variants) =================
// Tile: BM=BN=128, BK=16, 256 threads, 8x8 micro-tile, packed FFMA2 inner product,
// 2-stage smem ping-pong (1 barrier per k-step).

__device__ __forceinline__ void gemm_compute_step(const float (*As)[132],
                                                  const float (*Bs)[128],
                                                  int tx, int ty,
                                                  u64 acc2[8][4]) {
#pragma unroll
    for (int k = 0; k < 16; k++) {
        float a[8];
        *(float4*)&a[0] = *(const float4*)&As[k][ty * 8];
        *(float4*)&a[4] = *(const float4*)&As[k][ty * 8 + 4];
        u64 bp[4];
#pragma unroll
        for (int j = 0; j < 4; j++)
            bp[j] = *(const u64*)&Bs[k][tx * 8 + 2 * j];
#pragma unroll
        for (int i = 0; i < 8; i++) {
            u64 ad = dup2(a[i]);
#pragma unroll
            for (int j = 0; j < 4; j++)
                acc2[i][j] = fma2(ad, bp[j], acc2[i][j]);
        }
    }
}

__device__ __forceinline__ void gemm_store_tile(float (*As)[132], float (*Bs)[128],
                                                const float4 apre[2], const float4 bpre[2],
                                                int arow, int acol, int brow, int bcol) {
#pragma unroll
    for (int g = 0; g < 2; g++) {
        int m = arow + g * 64;
        As[acol + 0][m] = apre[g].x;
        As[acol + 1][m] = apre[g].y;
        As[acol + 2][m] = apre[g].z;
        As[acol + 3][m] = apre[g].w;
    }
#pragma unroll
    for (int g = 0; g < 2; g++) {
        *(float4*)&Bs[brow + g * 8][bcol] = bpre[g];
    }
}

template <bool ACCUM, bool BIAS, bool SILU>
__device__ __forceinline__ void gemm_epilogue(u64 acc2[8][4],
                                              const float* __restrict__ bias,
                                              float* __restrict__ C,
                                              int r0, int c0, int tx, int ty,
                                              int N, int M) {
#pragma unroll
    for (int i = 0; i < 8; i++) {
        int row = r0 + ty * 8 + i;
        if (row < N) {
            float accf[8];
#pragma unroll
            for (int j = 0; j < 4; j++)
                unpack2(acc2[i][j], accf[2 * j], accf[2 * j + 1]);
#pragma unroll
            for (int jv = 0; jv < 2; jv++) {
                int col = c0 + tx * 8 + jv * 4;
                if (col < M) {
                    float v0 = accf[jv * 4 + 0];
                    float v1 = accf[jv * 4 + 1];
                    float v2 = accf[jv * 4 + 2];
                    float v3 = accf[jv * 4 + 3];
                    float* cp = C + (size_t)row * M + col;
                    if (ACCUM) {
                        float4 pv = *(const float4*)cp;
                        v0 += pv.x; v1 += pv.y; v2 += pv.z; v3 += pv.w;
                    }
                    if (BIAS) {
                        float4 bv = *(const float4*)(bias + col);
                        v0 += bv.x; v1 += bv.y; v2 += bv.z; v3 += bv.w;
                    }
                    if (SILU) {
                        v0 = silu_f(v0); v1 = silu_f(v1);
                        v2 = silu_f(v2); v3 = silu_f(v3);
                    }
                    *(float4*)cp = make_float4(v0, v1, v2, v3);
                }
            }
        }
    }
}

// ---------------- generic fp32 GEMM: C = [act](([C] +) A@B (+ bias)) ----------------
// A: [N,K] row-major, B: [K,M] row-major, C: [N,M].
template <bool ACCUM, bool BIAS, bool SILU>
__global__ void __launch_bounds__(256, 2) gemm128_kernel(const float* __restrict__ A,
                                                         const float* __restrict__ B,
                                                         const float* __restrict__ bias,
                                                         float* __restrict__ C,
                                                         int N, int K, int M) {
    __shared__ float As[2][16][132];
    __shared__ float Bs[2][16][128];
    int tid = threadIdx.x;
    int r0 = blockIdx.y * 128;
    int c0 = blockIdx.x * 128;
    int tx = tid & 15;
    int ty = tid >> 4;

    u64 acc2[8][4];
#pragma unroll
    for (int i = 0; i < 8; i++)
#pragma unroll
        for (int j = 0; j < 4; j++) acc2[i][j] = 0ULL;

    int arow = tid >> 2;          // 0..63
    int acol = (tid & 3) * 4;     // 0,4,8,12
    int brow = tid >> 5;          // 0..7
    int bcol = (tid & 31) * 4;    // 0..124

    // prologue: fetch k-tile 0 and commit to stage 0
    float4 apre[2], bpre[2];
#pragma unroll
    for (int g = 0; g < 2; g++) {
        int grow = r0 + arow + g * 64;
        apre[g] = make_float4(0.f, 0.f, 0.f, 0.f);
        if (grow < N) apre[g] = *(const float4*)(A + (size_t)grow * K + acol);
    }
#pragma unroll
    for (int g = 0; g < 2; g++) {
        int k = brow + g * 8;
        int gcol = c0 + bcol;
        bpre[g] = make_float4(0.f, 0.f, 0.f, 0.f);
        if (gcol < M) bpre[g] = *(const float4*)(B + (size_t)k * M + gcol);
    }
    gemm_store_tile(As[0], Bs[0], apre, bpre, arow, acol, brow, bcol);
    __syncthreads();

    int nsteps = K >> 4;
    for (int step = 0; step < nsteps; step++) {
        int cur = step & 1;
        bool more = (step + 1 < nsteps);
        if (more) {
            int kk = (step + 1) << 4;
#pragma unroll
            for (int g = 0; g < 2; g++) {
                int grow = r0 + arow + g * 64;
                apre[g] = make_float4(0.f, 0.f, 0.f, 0.f);
                if (grow < N) apre[g] = *(const float4*)(A + (size_t)grow * K + kk + acol);
            }
#pragma unroll
            for (int g = 0; g < 2; g++) {
                int k = kk + brow + g * 8;
                int gcol = c0 + bcol;
                bpre[g] = make_float4(0.f, 0.f, 0.f, 0.f);
                if (gcol < M) bpre[g] = *(const float4*)(B + (size_t)k * M + gcol);
            }
        }
        gemm_compute_step(As[cur], Bs[cur], tx, ty, acc2);
        if (more) {
            gemm_store_tile(As[cur ^ 1], Bs[cur ^ 1], apre, bpre, arow, acol, brow, bcol);
            __syncthreads();
        }
    }

    gemm_epilogue<ACCUM, BIAS, SILU>(acc2, bias, C, r0, c0, tx, ty, N, M);
}

// ---------------- fused U/V projection: blockIdx.z selects (B,C) pair ----------------
// A: [N,128] shared; z=0: C0 = A@B0 ; z=1: C1 = A@B1. K=M=128 fixed.
__global__ void __launch_bounds__(256, 2) gemm_uv_kernel(const float* __restrict__ A,
                                                         const float* __restrict__ B0,
                                                         const float* __restrict__ B1,
                                                         float* __restrict__ C0,
                                                         float* __restrict__ C1,
                                                         int N) {
    const float* B = (blockIdx.z == 0) ? B0 : B1;
    float* C = (blockIdx.z == 0) ? C0 : C1;

    __shared__ float As[2][16][132];
    __shared__ float Bs[2][16][128];
    int tid = threadIdx.x;
    int r0 = blockIdx.y * 128;
    int tx = tid & 15;
    int ty = tid >> 4;

    u64 acc2[8][4];
#pragma unroll
    for (int i = 0; i < 8; i++)
#pragma unroll
        for (int j = 0; j < 4; j++) acc2[i][j] = 0ULL;

    int arow = tid >> 2;
    int acol = (tid & 3) * 4;
    int brow = tid >> 5;
    int bcol = (tid & 31) * 4;

    float4 apre[2], bpre[2];
#pragma unroll
    for (int g = 0; g < 2; g++) {
        int grow = r0 + arow + g * 64;
        apre[g] = make_float4(0.f, 0.f, 0.f, 0.f);
        if (grow < N) apre[g] = *(const float4*)(A + (size_t)grow * 128 + acol);
    }
#pragma unroll
    for (int g = 0; g < 2; g++)
        bpre[g] = *(const float4*)(B + (size_t)(brow + g * 8) * 128 + bcol);
    gemm_store_tile(As[0], Bs[0], apre, bpre, arow, acol, brow, bcol);
    __syncthreads();

    for (int step = 0; step < 8; step++) {
        int cur = step & 1;
        bool more = (step + 1 < 8);
        if (more) {
            int kk = (step + 1) << 4;
#pragma unroll
            for (int g = 0; g < 2; g++) {
                int grow = r0 + arow + g * 64;
                apre[g] = make_float4(0.f, 0.f, 0.f, 0.f);
                if (grow < N) apre[g] = *(const float4*)(A + (size_t)grow * 128 + kk + acol);
            }
#pragma unroll
            for (int g = 0; g < 2; g++)
                bpre[g] = *(const float4*)(B + (size_t)(kk + brow + g * 8) * 128 + bcol);
        }
        gemm_compute_step(As[cur], Bs[cur], tx, ty, acc2);
        if (more) {
            gemm_store_tile(As[cur ^ 1], Bs[cur ^ 1], apre, bpre, arow, acol, brow, bcol);
            __syncthreads();
        }
    }

    gemm_epilogue<false, false, false>(acc2, nullptr, C, r0, 0, tx, ty, N, 128);
}

// ---------------- dual-A GEMM: C = silu([A1|A2] @ B + bias) ----------------
// A1,A2: [N,128]; B: [256,128] contiguous; C: [N,128]. K=256 (steps 0..7 from A1,
// 8..15 from A2). Accumulation order identical to GEMM(A1)+ACCUM-GEMM(A2).
__global__ void __launch_bounds__(256, 2) gemm_dualA_kernel(const float* __restrict__ A1,
                                                            const float* __restrict__ A2,
                                                            const float* __restrict__ B,
                                                            const float* __restrict__ bias,
                                                            float* __restrict__ C,
                                                            int N) {
    __shared__ float As[2][16][132];
    __shared__ float Bs[2][16][128];
    int tid = threadIdx.x;
    int r0 = blockIdx.y * 128;
    int tx = tid & 15;
    int ty = tid >> 4;

    u64 acc2[8][4];
#pragma unroll
    for (int i = 0; i < 8; i++)
#pragma unroll
        for (int j = 0; j < 4; j++) acc2[i][j] = 0ULL;

    int arow = tid >> 2;
    int acol = (tid & 3) * 4;
    int brow = tid >> 5;
    int bcol = (tid & 31) * 4;

    float4 apre[2], bpre[2];
#pragma unroll
    for (int g = 0; g < 2; g++) {
        int grow = r0 + arow + g * 64;
        apre[g] = make_float4(0.f, 0.f, 0.f, 0.f);
        if (grow < N) apre[g] = *(const float4*)(A1 + (size_t)grow * 128 + acol);
    }
#pragma unroll
    for (int g = 0; g < 2; g++)
        bpre[g] = *(const float4*)(B + (size_t)(brow + g * 8) * 128 + bcol);
    gemm_store_tile(As[0], Bs[0], apre, bpre, arow, acol, brow, bcol);
    __syncthreads();

    for (int step = 0; step < 16; step++) {
        int cur = step & 1;
        bool more = (step + 1 < 16);
        if (more) {
            int kk = (step + 1) << 4;
            const float* Ap = (kk < 128) ? A1 : A2;
            int ak = kk & 127;
#pragma unroll
            for (int g = 0; g < 2; g++) {
                int grow = r0 + arow + g * 64;
                apre[g] = make_float4(0.f, 0.f, 0.f, 0.f);
                if (grow < N) apre[g] = *(const float4*)(Ap + (size_t)grow * 128 + ak + acol);
            }
#pragma unroll
            for (int g = 0; g < 2; g++)
                bpre[g] = *(const float4*)(B + (size_t)(kk + brow + g * 8) * 128 + bcol);
        }
        gemm_compute_step(As[cur], Bs[cur], tx, ty, acc2);
        if (more) {
            gemm_store_tile(As[cur ^ 1], Bs[cur ^ 1], apre, bpre, arow, acol, brow, bcol);
            __syncthreads();
        }
    }

    gemm_epilogue<false, true, true>(acc2, bias, C, r0, 0, tx, ty, N, 128);
}

// ---------------- edge messages (active edges only, warp per edge) ----------------
__global__ void edge_msg_kernel(const float* __restrict__ W,   // [20,384] for layer l
                                const float* __restrict__ b,   // [384]
                                const float* __restrict__ s) { // [N,384]
    int lane = threadIdx.x & 31;
    int warp = (blockIdx.x * blockDim.x + threadIdx.x) >> 5;
    int nwarps = (gridDim.x * blockDim.x) >> 5;
    int nact = g_nact;
    for (int e = warp; e < nact; e += nwarps) {
        int r = g_act_r[e];
        int c = g_act_c[e];
        float fcut = g_act_fcut[e];
        float u0 = g_act_unit[e * 3 + 0];
        float u1 = g_act_unit[e * 3 + 1];
        float u2 = g_act_unit[e * 3 + 2];
        float rbf[NRBF];
#pragma unroll
        for (int t = 0; t < NRBF; t++) rbf[t] = g_act_rbf[e * NRBF + t];

        float fout[12];
#pragma unroll
        for (int p = 0; p < 12; p++) {
            int j = lane + p * 32;
            float f = b[j];
#pragma unroll
            for (int t = 0; t < NRBF; t++) f += rbf[t] * W[t * 384 + j];
            fout[p] = f * fcut * s[(size_t)c * 384 + j];
        }
#pragma unroll
        for (int q = 0; q < 4; q++) {
            int h = lane + q * 32;
            float gsv = fout[q];
            float gev = fout[4 + q];
            float msg = fout[8 + q];
            atomicAdd(&g_ns[r * HID + h], msg);
            int rb = r * 3 * HID + h;
            int cb = c * 3 * HID + h;
            atomicAdd(&g_nv[rb], g_nvold[cb] * gsv + gev * u0);
            atomicAdd(&g_nv[rb + HID], g_nvold[cb + HID] * gsv + gev * u1);
            atomicAdd(&g_nv[rb + 2 * HID], g_nvold[cb + 2 * HID] * gsv + gev * u2);
        }
    }
}

// ---------------- Vnorm + inner product ----------------
__global__ void vnorm_inner_kernel(int N) {
    int t = blockIdx.x * blockDim.x + threadIdx.x;
    if (t >= N * HID) return;
    int n = t >> 7;
    int h = t & 127;
    size_t base = (size_t)n * 3 * HID + h;
    float u0 = g_Uv[base], u1 = g_Uv[base + HID], u2 = g_Uv[base + 2 * HID];
    float v0 = g_Vv[base], v1 = g_Vv[base + HID], v2 = g_Vv[base + 2 * HID];
    g_Vn[t] = sqrtf(v0 * v0 + v1 * v1 + v2 * v2);
    g_inner[t] = u0 * v0 + u1 * v1 + u2 * v2;
}

// -------- final update: nv += a_vv*Uv ; ns += inner*a_sv + a_ss ; nvold = nv --------
__global__ void update_kernel(int N) {
    int t = blockIdx.x * blockDim.x + threadIdx.x;
    if (t >= N * HID) return;
    int n = t >> 7;
    int h = t & 127;
    size_t base = (size_t)n * 3 * HID + h;
    float avv = g_abuf[base];
    float asv = g_abuf[base + HID];
    float ass = g_abuf[base + 2 * HID];
    float n0 = g_nv[base]           + avv * g_Uv[base];
    float n1 = g_nv[base + HID]     + avv * g_Uv[base + HID];
    float n2 = g_nv[base + 2 * HID] + avv * g_Uv[base + 2 * HID];
    g_nv[base] = n0;            g_nvold[base] = n0;
    g_nv[base + HID] = n1;      g_nvold[base + HID] = n1;
    g_nv[base + 2 * HID] = n2;  g_nvold[base + 2 * HID] = n2;
    g_ns[t] += g_inner[t] * asv + ass;
}

// ---------------- head second layer (matvec over 64) ----------------
__global__ void head2_kernel(const float* __restrict__ w,  // [64]
                             const float* __restrict__ b,  // [1]
                             float* __restrict__ out_v, int N) {
    int n = blockIdx.x * blockDim.x + threadIdx.x;
    if (n >= N) return;
    float acc = b[0];
    const float* h = g_tmpH + (size_t)n * 64;
#pragma unroll
    for (int i = 0; i < 64; i++) acc += h[i] * w[i];
    out_v[n] = acc;
}

// ---------------- launch ----------------
static inline dim3 gemm_grid(int M, int N) {
    return dim3((M + 127) / 128, (N + 127) / 128);
}

extern "C" void kernel_launch(void* const* d_in, const int* in_sizes, int n_in,
                              void* d_out, int out_size) {
    const int*   z        = (const int*)d_in[0];
    const float* pos      = (const float*)d_in[1];
    const float* cell     = (const float*)d_in[2];
    const int*   ei       = (const int*)d_in[3];
    const int*   offs     = (const int*)d_in[4];
    const float* embed    = (const float*)d_in[5];
    const float* mfW      = (const float*)d_in[6];   // [3,20,384]
    const float* mfb      = (const float*)d_in[7];   // [3,384]
    const float* mW1      = (const float*)d_in[8];   // [3,128,128]
    const float* mb1      = (const float*)d_in[9];
    const float* mW2      = (const float*)d_in[10];  // [3,128,384]
    const float* mb2      = (const float*)d_in[11];
    const float* uU       = (const float*)d_in[12];  // [3,128,128]
    const float* uV       = (const float*)d_in[13];
    const float* uW1      = (const float*)d_in[14];  // [3,256,128]
    const float* ub1      = (const float*)d_in[15];
    const float* uW2      = (const float*)d_in[16];  // [3,128,384]
    const float* ub2      = (const float*)d_in[17];
    const float* hW1      = (const float*)d_in[18];  // [128,64]
    const float* hb1      = (const float*)d_in[19];
    const float* hW2      = (const float*)d_in[20];  // [64]
    const float* hb2      = (const float*)d_in[21];

    int N = in_sizes[0];
    int E = in_sizes[3] / 2;

    float* out   = (float*)d_out;
    float* out_v = out;                  // [N]
    float* out_p = out + N;              // [N*3]
    float* out_e = out + 4 * N;          // [2*E]
    float* out_d = out + 4 * N + 2 * E;  // [E]

    // device-global scratch pointers
    void* p;
    cudaGetSymbolAddress(&p, g_ns);    float* ns    = (float*)p;
    cudaGetSymbolAddress(&p, g_nv);    float* nv    = (float*)p;
    cudaGetSymbolAddress(&p, g_tmpH);  float* tmpH  = (float*)p;
    cudaGetSymbolAddress(&p, g_smsg);  float* smsg  = (float*)p;
    cudaGetSymbolAddress(&p, g_Uv);    float* Uv    = (float*)p;
    cudaGetSymbolAddress(&p, g_Vv);    float* Vv    = (float*)p;
    cudaGetSymbolAddress(&p, g_Vn);    float* Vn    = (float*)p;
    cudaGetSymbolAddress(&p, g_abuf);  float* abuf  = (float*)p;

    reset_kernel<<<1, 1>>>();
    edge_geom_kernel<<<(E + 255) / 256, 256>>>(pos, cell, ei, offs, out_d, out_e, E);
    init_nodes_kernel<<<(N * HID + 255) / 256, 256>>>(embed, z, N);
    cudaMemcpyAsync(out_p, pos, (size_t)N * 3 * sizeof(float), cudaMemcpyDeviceToDevice);

    for (int l = 0; l < 3; l++) {
        const float* lmfW = mfW + (size_t)l * 20 * 384;
        const float* lmfb = mfb + (size_t)l * 384;

        // s = silu(ns @ mW1 + mb1) @ mW2 + mb2
        gemm128_kernel<false, true, true><<<gemm_grid(128, N), 256>>>(
            ns, mW1 + (size_t)l * 128 * 128, mb1 + (size_t)l * 128, tmpH, N, 128, 128);
        gemm128_kernel<false, true, false><<<gemm_grid(384, N), 256>>>(
            tmpH, mW2 + (size_t)l * 128 * 384, mb2 + (size_t)l * 384, smsg, N, 128, 384);

        // edge messages read g_nvold (pre-message state, maintained by dual-write)
        edge_msg_kernel<<<256, 256>>>(lmfW, lmfb, smsg);

        // Uv = nv @ U ; Vv = nv @ V  (nv viewed as [3N,128]; fused, z selects B/C)
        {
            dim3 g(1, (3 * N + 127) / 128, 2);
            gemm_uv_kernel<<<g, 256>>>(nv,
                                       uU + (size_t)l * 128 * 128,
                                       uV + (size_t)l * 128 * 128,
                                       Uv, Vv, 3 * N);
        }

        vnorm_inner_kernel<<<(N * HID + 255) / 256, 256>>>(N);

        // hidden = silu([ns|Vn] @ uW1 + b1)   (dual-A, K=256, single pass)
        {
            dim3 g(1, (N + 127) / 128, 1);
            gemm_dualA_kernel<<<g, 256>>>(ns, Vn,
                                          uW1 + (size_t)l * 256 * 128,
                                          ub1 + (size_t)l * 128, tmpH, N);
        }
        // a = hidden @ W2 + b2
        gemm128_kernel<false, true, false><<<gemm_grid(384, N), 256>>>(
            tmpH, uW2 + (size_t)l * 128 * 384, ub2 + (size_t)l * 384, abuf, N, 128, 384);

        update_kernel<<<(N * HID + 255) / 256, 256>>>(N);
    }

    // head
    gemm128_kernel<false, true, true><<<gemm_grid(64, N), 256>>>(
        ns, hW1, hb1, tmpH, N, 128, 64);
    head2_kernel<<<(N + 255) / 256, 256>>>(hW2, hb2, out_v, N);
}

// round 9
// speedup vs baseline: 1.0954x; 1.0954x over previous
#include <cuda_runtime.h>
#include <math.h>
#include <stdint.h>

#define HID 128
#define NMAX 50000
#define EMAX 500000
#define NRBF 20
#define PI_OVER_CUT 0.5235987755982988f   // pi / 6
#define CUTOFF 6.0f

typedef unsigned long long u64;

// ---------------- scratch (device globals; no runtime allocation) ----------------
__device__ float g_ns[NMAX * HID];
__device__ float g_nv[NMAX * 3 * HID];
__device__ float g_nvold[NMAX * 3 * HID];
__device__ float g_tmpH[NMAX * HID];
__device__ float g_smsg[NMAX * 3 * HID];
__device__ float g_Uv[NMAX * 3 * HID];
__device__ float g_Vv[NMAX * 3 * HID];
__device__ float g_Vn[NMAX * HID];
__device__ float g_inner[NMAX * HID];
__device__ float g_abuf[NMAX * 3 * HID];

__device__ int   g_act_r[EMAX];
__device__ int   g_act_c[EMAX];
__device__ float g_act_unit[EMAX * 3];
__device__ float g_act_rbf[EMAX * NRBF];
__device__ float g_act_fcut[EMAX];
__device__ int   g_nact;

__device__ __forceinline__ float silu_f(float x) {
    return x / (1.0f + __expf(-x));
}

// packed f32x2 helpers (sm_100+; SASS FFMA2 — ptxas never emits this from C++)
__device__ __forceinline__ u64 fma2(u64 a, u64 b, u64 c) {
    u64 d;
    asm("fma.rn.f32x2 %0, %1, %2, %3;" : "=l"(d) : "l"(a), "l"(b), "l"(c));
    return d;
}
__device__ __forceinline__ u64 dup2(float x) {
    u64 d;
    asm("mov.b64 %0, {%1, %1};" : "=l"(d) : "f"(x));
    return d;
}
__device__ __forceinline__ void unpack2(u64 v, float& lo, float& hi) {
    asm("mov.b64 {%0, %1}, %2;" : "=f"(lo), "=f"(hi) : "l"(v));
}

// warp-shaped thread->tile mapping: warp = 4 rows x 8 cols of 8x8 micro-tiles.
// Per-warp unique fragment data per k-step: a=128B, b=256B (vs 64B/512B row-major).
__device__ __forceinline__ void tile_coords(int tid, int& tx, int& ty) {
    int w = tid >> 5, l = tid & 31;
    ty = (w & 3) * 4 + (l & 3);    // 0..15
    tx = (w >> 2) * 8 + (l >> 2);  // 0..15
}

// ---------------- reset ----------------
__global__ void reset_kernel() { g_nact = 0; }

// ---------------- edge geometry + compaction ----------------
__global__ void edge_geom_kernel(const float* __restrict__ pos,
                                 const float* __restrict__ cell,
                                 const int* __restrict__ ei,
                                 const int* __restrict__ offs,
                                 float* __restrict__ out_dist,
                                 float* __restrict__ out_ei,
                                 int E) {
    int e = blockIdx.x * blockDim.x + threadIdx.x;
    if (e >= E) return;
    int r = ei[e];
    int c = ei[E + e];
    float o0 = (float)offs[e * 3 + 0];
    float o1 = (float)offs[e * 3 + 1];
    float o2 = (float)offs[e * 3 + 2];
    float ox = o0 * cell[0] + o1 * cell[3] + o2 * cell[6];
    float oy = o0 * cell[1] + o1 * cell[4] + o2 * cell[7];
    float oz = o0 * cell[2] + o1 * cell[5] + o2 * cell[8];
    float dx = pos[r * 3 + 0] - pos[c * 3 + 0] + ox;
    float dy = pos[r * 3 + 1] - pos[c * 3 + 1] + oy;
    float dz = pos[r * 3 + 2] - pos[c * 3 + 2] + oz;
    float dist = sqrtf(dx * dx + dy * dy + dz * dz);
    out_dist[e] = dist;
    out_ei[e] = (float)r;
    out_ei[E + e] = (float)c;

    if (dist < CUTOFF) {
        int idx = atomicAdd(&g_nact, 1);
        g_act_r[idx] = r;
        g_act_c[idx] = c;
        float inv = 1.0f / dist;
        g_act_unit[idx * 3 + 0] = dx * inv;
        g_act_unit[idx * 3 + 1] = dy * inv;
        g_act_unit[idx * 3 + 2] = dz * inv;
        g_act_fcut[idx] = 0.5f * (cosf(dist * PI_OVER_CUT) + 1.0f);
#pragma unroll
        for (int t = 0; t < NRBF; t++) {
            g_act_rbf[idx * NRBF + t] = sinf(dist * (float)(t + 1) * PI_OVER_CUT) * inv;
        }
    }
}

// ---------------- node init: ns = embed[z], nv = nvold = 0 ----------------
__global__ void init_nodes_kernel(const float* __restrict__ embed,
                                  const int* __restrict__ z,
                                  int N) {
    int t = blockIdx.x * blockDim.x + threadIdx.x;
    if (t >= N * HID) return;
    int n = t >> 7;
    int h = t & 127;
    g_ns[t] = embed[z[n] * HID + h];
    int base = n * 3 * HID + h;
    g_nv[base] = 0.0f;
    g_nv[base + HID] = 0.0f;
    g_nv[base + 2 * HID] = 0.0f;
    g_nvold[base] = 0.0f;
    g_nvold[base + HID] = 0.0f;
    g_nvold[base + 2 * HID] = 0.0f;
}

// ================= GEMM core pieces (shared by the variants) =================
// Tile: BM=BN=128, BK=16, 256 threads, 8x8 micro-tile, packed FFMA2 inner product,
// 2-stage smem ping-pong (1 barrier per k-step), 4x8 warp footprint,
// b-fragment via 2x LDS.128.

__device__ __forceinline__ void gemm_compute_step(const float (*As)[132],
                                                  const float (*Bs)[128],
                                                  int tx, int ty,
                                                  u64 acc2[8][4]) {
#pragma unroll
    for (int k = 0; k < 16; k++) {
        float a[8];
        *(float4*)&a[0] = *(const float4*)&As[k][ty * 8];
        *(float4*)&a[4] = *(const float4*)&As[k][ty * 8 + 4];
        float4 bv0 = *(const float4*)&Bs[k][tx * 8];
        float4 bv1 = *(const float4*)&Bs[k][tx * 8 + 4];
        u64 bp[4];
        bp[0] = *(const u64*)&bv0.x;
        bp[1] = *(const u64*)&bv0.z;
        bp[2] = *(const u64*)&bv1.x;
        bp[3] = *(const u64*)&bv1.z;
#pragma unroll
        for (int i = 0; i < 8; i++) {
            u64 ad = dup2(a[i]);
#pragma unroll
            for (int j = 0; j < 4; j++)
                acc2[i][j] = fma2(ad, bp[j], acc2[i][j]);
        }
    }
}

__device__ __forceinline__ void gemm_store_tile(float (*As)[132], float (*Bs)[128],
                                                const float4 apre[2], const float4 bpre[2],
                                                int arow, int acol, int brow, int bcol) {
#pragma unroll
    for (int g = 0; g < 2; g++) {
        int m = arow + g * 64;
        As[acol + 0][m] = apre[g].x;
        As[acol + 1][m] = apre[g].y;
        As[acol + 2][m] = apre[g].z;
        As[acol + 3][m] = apre[g].w;
    }
#pragma unroll
    for (int g = 0; g < 2; g++) {
        *(float4*)&Bs[brow + g * 8][bcol] = bpre[g];
    }
}

template <bool ACCUM, bool BIAS, bool SILU>
__device__ __forceinline__ void gemm_epilogue(u64 acc2[8][4],
                                              const float* __restrict__ bias,
                                              float* __restrict__ C,
                                              int r0, int c0, int tx, int ty,
                                              int N, int M) {
#pragma unroll
    for (int i = 0; i < 8; i++) {
        int row = r0 + ty * 8 + i;
        if (row < N) {
            float accf[8];
#pragma unroll
            for (int j = 0; j < 4; j++)
                unpack2(acc2[i][j], accf[2 * j], accf[2 * j + 1]);
#pragma unroll
            for (int jv = 0; jv < 2; jv++) {
                int col = c0 + tx * 8 + jv * 4;
                if (col < M) {
                    float v0 = accf[jv * 4 + 0];
                    float v1 = accf[jv * 4 + 1];
                    float v2 = accf[jv * 4 + 2];
                    float v3 = accf[jv * 4 + 3];
                    float* cp = C + (size_t)row * M + col;
                    if (ACCUM) {
                        float4 pv = *(const float4*)cp;
                        v0 += pv.x; v1 += pv.y; v2 += pv.z; v3 += pv.w;
                    }
                    if (BIAS) {
                        float4 bv = *(const float4*)(bias + col);
                        v0 += bv.x; v1 += bv.y; v2 += bv.z; v3 += bv.w;
                    }
                    if (SILU) {
                        v0 = silu_f(v0); v1 = silu_f(v1);
                        v2 = silu_f(v2); v3 = silu_f(v3);
                    }
                    *(float4*)cp = make_float4(v0, v1, v2, v3);
                }
            }
        }
    }
}

// ---------------- generic fp32 GEMM: C = [act](([C] +) A@B (+ bias)) ----------------
template <bool ACCUM, bool BIAS, bool SILU>
__global__ void __launch_bounds__(256, 2) gemm128_kernel(const float* __restrict__ A,
                                                         const float* __restrict__ B,
                                                         const float* __restrict__ bias,
                                                         float* __restrict__ C,
                                                         int N, int K, int M) {
    __shared__ float As[2][16][132];
    __shared__ float Bs[2][16][128];
    int tid = threadIdx.x;
    int r0 = blockIdx.y * 128;
    int c0 = blockIdx.x * 128;
    int tx, ty;
    tile_coords(tid, tx, ty);

    u64 acc2[8][4];
#pragma unroll
    for (int i = 0; i < 8; i++)
#pragma unroll
        for (int j = 0; j < 4; j++) acc2[i][j] = 0ULL;

    int arow = tid >> 2;          // 0..63
    int acol = (tid & 3) * 4;     // 0,4,8,12
    int brow = tid >> 5;          // 0..7
    int bcol = (tid & 31) * 4;    // 0..124

    float4 apre[2], bpre[2];
#pragma unroll
    for (int g = 0; g < 2; g++) {
        int grow = r0 + arow + g * 64;
        apre[g] = make_float4(0.f, 0.f, 0.f, 0.f);
        if (grow < N) apre[g] = *(const float4*)(A + (size_t)grow * K + acol);
    }
#pragma unroll
    for (int g = 0; g < 2; g++) {
        int k = brow + g * 8;
        int gcol = c0 + bcol;
        bpre[g] = make_float4(0.f, 0.f, 0.f, 0.f);
        if (gcol < M) bpre[g] = *(const float4*)(B + (size_t)k * M + gcol);
    }
    gemm_store_tile(As[0], Bs[0], apre, bpre, arow, acol, brow, bcol);
    __syncthreads();

    int nsteps = K >> 4;
    for (int step = 0; step < nsteps; step++) {
        int cur = step & 1;
        bool more = (step + 1 < nsteps);
        if (more) {
            int kk = (step + 1) << 4;
#pragma unroll
            for (int g = 0; g < 2; g++) {
                int grow = r0 + arow + g * 64;
                apre[g] = make_float4(0.f, 0.f, 0.f, 0.f);
                if (grow < N) apre[g] = *(const float4*)(A + (size_t)grow * K + kk + acol);
            }
#pragma unroll
            for (int g = 0; g < 2; g++) {
                int k = kk + brow + g * 8;
                int gcol = c0 + bcol;
                bpre[g] = make_float4(0.f, 0.f, 0.f, 0.f);
                if (gcol < M) bpre[g] = *(const float4*)(B + (size_t)k * M + gcol);
            }
        }
        gemm_compute_step(As[cur], Bs[cur], tx, ty, acc2);
        if (more) {
            gemm_store_tile(As[cur ^ 1], Bs[cur ^ 1], apre, bpre, arow, acol, brow, bcol);
            __syncthreads();
        }
    }

    gemm_epilogue<ACCUM, BIAS, SILU>(acc2, bias, C, r0, c0, tx, ty, N, M);
}

// ---------------- fused U/V projection: blockIdx.z selects (B,C) pair ----------------
__global__ void __launch_bounds__(256, 2) gemm_uv_kernel(const float* __restrict__ A,
                                                         const float* __restrict__ B0,
                                                         const float* __restrict__ B1,
                                                         float* __restrict__ C0,
                                                         float* __restrict__ C1,
                                                         int N) {
    const float* B = (blockIdx.z == 0) ? B0 : B1;
    float* C = (blockIdx.z == 0) ? C0 : C1;

    __shared__ float As[2][16][132];
    __shared__ float Bs[2][16][128];
    int tid = threadIdx.x;
    int r0 = blockIdx.y * 128;
    int tx, ty;
    tile_coords(tid, tx, ty);

    u64 acc2[8][4];
#pragma unroll
    for (int i = 0; i < 8; i++)
#pragma unroll
        for (int j = 0; j < 4; j++) acc2[i][j] = 0ULL;

    int arow = tid >> 2;
    int acol = (tid & 3) * 4;
    int brow = tid >> 5;
    int bcol = (tid & 31) * 4;

    float4 apre[2], bpre[2];
#pragma unroll
    for (int g = 0; g < 2; g++) {
        int grow = r0 + arow + g * 64;
        apre[g] = make_float4(0.f, 0.f, 0.f, 0.f);
        if (grow < N) apre[g] = *(const float4*)(A + (size_t)grow * 128 + acol);
    }
#pragma unroll
    for (int g = 0; g < 2; g++)
        bpre[g] = *(const float4*)(B + (size_t)(brow + g * 8) * 128 + bcol);
    gemm_store_tile(As[0], Bs[0], apre, bpre, arow, acol, brow, bcol);
    __syncthreads();

    for (int step = 0; step < 8; step++) {
        int cur = step & 1;
        bool more = (step + 1 < 8);
        if (more) {
            int kk = (step + 1) << 4;
#pragma unroll
            for (int g = 0; g < 2; g++) {
                int grow = r0 + arow + g * 64;
                apre[g] = make_float4(0.f, 0.f, 0.f, 0.f);
                if (grow < N) apre[g] = *(const float4*)(A + (size_t)grow * 128 + kk + acol);
            }
#pragma unroll
            for (int g = 0; g < 2; g++)
                bpre[g] = *(const float4*)(B + (size_t)(kk + brow + g * 8) * 128 + bcol);
        }
        gemm_compute_step(As[cur], Bs[cur], tx, ty, acc2);
        if (more) {
            gemm_store_tile(As[cur ^ 1], Bs[cur ^ 1], apre, bpre, arow, acol, brow, bcol);
            __syncthreads();
        }
    }

    gemm_epilogue<false, false, false>(acc2, nullptr, C, r0, 0, tx, ty, N, 128);
}

// ---------------- dual-A GEMM: C = silu([A1|A2] @ B + bias) ----------------
__global__ void __launch_bounds__(256, 2) gemm_dualA_kernel(const float* __restrict__ A1,
                                                            const float* __restrict__ A2,
                                                            const float* __restrict__ B,
                                                            const float* __restrict__ bias,
                                                            float* __restrict__ C,
                                                            int N) {
    __shared__ float As[2][16][132];
    __shared__ float Bs[2][16][128];
    int tid = threadIdx.x;
    int r0 = blockIdx.y * 128;
    int tx, ty;
    tile_coords(tid, tx, ty);

    u64 acc2[8][4];
#pragma unroll
    for (int i = 0; i < 8; i++)
#pragma unroll
        for (int j = 0; j < 4; j++) acc2[i][j] = 0ULL;

    int arow = tid >> 2;
    int acol = (tid & 3) * 4;
    int brow = tid >> 5;
    int bcol = (tid & 31) * 4;

    float4 apre[2], bpre[2];
#pragma unroll
    for (int g = 0; g < 2; g++) {
        int grow = r0 + arow + g * 64;
        apre[g] = make_float4(0.f, 0.f, 0.f, 0.f);
        if (grow < N) apre[g] = *(const float4*)(A1 + (size_t)grow * 128 + acol);
    }
#pragma unroll
    for (int g = 0; g < 2; g++)
        bpre[g] = *(const float4*)(B + (size_t)(brow + g * 8) * 128 + bcol);
    gemm_store_tile(As[0], Bs[0], apre, bpre, arow, acol, brow, bcol);
    __syncthreads();

    for (int step = 0; step < 16; step++) {
        int cur = step & 1;
        bool more = (step + 1 < 16);
        if (more) {
            int kk = (step + 1) << 4;
            const float* Ap = (kk < 128) ? A1 : A2;
            int ak = kk & 127;
#pragma unroll
            for (int g = 0; g < 2; g++) {
                int grow = r0 + arow + g * 64;
                apre[g] = make_float4(0.f, 0.f, 0.f, 0.f);
                if (grow < N) apre[g] = *(const float4*)(Ap + (size_t)grow * 128 + ak + acol);
            }
#pragma unroll
            for (int g = 0; g < 2; g++)
                bpre[g] = *(const float4*)(B + (size_t)(kk + brow + g * 8) * 128 + bcol);
        }
        gemm_compute_step(As[cur], Bs[cur], tx, ty, acc2);
        if (more) {
            gemm_store_tile(As[cur ^ 1], Bs[cur ^ 1], apre, bpre, arow, acol, brow, bcol);
            __syncthreads();
        }
    }

    gemm_epilogue<false, true, true>(acc2, bias, C, r0, 0, tx, ty, N, 128);
}

// ---------------- edge messages (active edges only, warp per edge) ----------------
__global__ void edge_msg_kernel(const float* __restrict__ W,   // [20,384] for layer l
                                const float* __restrict__ b,   // [384]
                                const float* __restrict__ s) { // [N,384]
    int lane = threadIdx.x & 31;
    int warp = (blockIdx.x * blockDim.x + threadIdx.x) >> 5;
    int nwarps = (gridDim.x * blockDim.x) >> 5;
    int nact = g_nact;
    for (int e = warp; e < nact; e += nwarps) {
        int r = g_act_r[e];
        int c = g_act_c[e];
        float fcut = g_act_fcut[e];
        float u0 = g_act_unit[e * 3 + 0];
        float u1 = g_act_unit[e * 3 + 1];
        float u2 = g_act_unit[e * 3 + 2];
        float rbf[NRBF];
#pragma unroll
        for (int t = 0; t < NRBF; t++) rbf[t] = g_act_rbf[e * NRBF + t];

        float fout[12];
#pragma unroll
        for (int p = 0; p < 12; p++) {
            int j = lane + p * 32;
            float f = b[j];
#pragma unroll
            for (int t = 0; t < NRBF; t++) f += rbf[t] * W[t * 384 + j];
            fout[p] = f * fcut * s[(size_t)c * 384 + j];
        }
#pragma unroll
        for (int q = 0; q < 4; q++) {
            int h = lane + q * 32;
            float gsv = fout[q];
            float gev = fout[4 + q];
            float msg = fout[8 + q];
            atomicAdd(&g_ns[r * HID + h], msg);
            int rb = r * 3 * HID + h;
            int cb = c * 3 * HID + h;
            atomicAdd(&g_nv[rb], g_nvold[cb] * gsv + gev * u0);
            atomicAdd(&g_nv[rb + HID], g_nvold[cb + HID] * gsv + gev * u1);
            atomicAdd(&g_nv[rb + 2 * HID], g_nvold[cb + 2 * HID] * gsv + gev * u2);
        }
    }
}

// ---------------- Vnorm + inner product ----------------
__global__ void vnorm_inner_kernel(int N) {
    int t = blockIdx.x * blockDim.x + threadIdx.x;
    if (t >= N * HID) return;
    int n = t >> 7;
    int h = t & 127;
    size_t base = (size_t)n * 3 * HID + h;
    float u0 = g_Uv[base], u1 = g_Uv[base + HID], u2 = g_Uv[base + 2 * HID];
    float v0 = g_Vv[base], v1 = g_Vv[base + HID], v2 = g_Vv[base + 2 * HID];
    g_Vn[t] = sqrtf(v0 * v0 + v1 * v1 + v2 * v2);
    g_inner[t] = u0 * v0 + u1 * v1 + u2 * v2;
}

// -------- final update: nv += a_vv*Uv ; ns += inner*a_sv + a_ss ; nvold = nv --------
__global__ void update_kernel(int N) {
    int t = blockIdx.x * blockDim.x + threadIdx.x;
    if (t >= N * HID) return;
    int n = t >> 7;
    int h = t & 127;
    size_t base = (size_t)n * 3 * HID + h;
    float avv = g_abuf[base];
    float asv = g_abuf[base + HID];
    float ass = g_abuf[base + 2 * HID];
    float n0 = g_nv[base]           + avv * g_Uv[base];
    float n1 = g_nv[base + HID]     + avv * g_Uv[base + HID];
    float n2 = g_nv[base + 2 * HID] + avv * g_Uv[base + 2 * HID];
    g_nv[base] = n0;            g_nvold[base] = n0;
    g_nv[base + HID] = n1;      g_nvold[base + HID] = n1;
    g_nv[base + 2 * HID] = n2;  g_nvold[base + 2 * HID] = n2;
    g_ns[t] += g_inner[t] * asv + ass;
}

// ---------------- head second layer (matvec over 64) ----------------
__global__ void head2_kernel(const float* __restrict__ w,  // [64]
                             const float* __restrict__ b,  // [1]
                             float* __restrict__ out_v, int N) {
    int n = blockIdx.x * blockDim.x + threadIdx.x;
    if (n >= N) return;
    float acc = b[0];
    const float* h = g_tmpH + (size_t)n * 64;
#pragma unroll
    for (int i = 0; i < 64; i++) acc += h[i] * w[i];
    out_v[n] = acc;
}

// ---------------- launch ----------------
static inline dim3 gemm_grid(int M, int N) {
    return dim3((M + 127) / 128, (N + 127) / 128);
}

extern "C" void kernel_launch(void* const* d_in, const int* in_sizes, int n_in,
                              void* d_out, int out_size) {
    const int*   z        = (const int*)d_in[0];
    const float* pos      = (const float*)d_in[1];
    const float* cell     = (const float*)d_in[2];
    const int*   ei       = (const int*)d_in[3];
    const int*   offs     = (const int*)d_in[4];
    const float* embed    = (const float*)d_in[5];
    const float* mfW      = (const float*)d_in[6];   // [3,20,384]
    const float* mfb      = (const float*)d_in[7];   // [3,384]
    const float* mW1      = (const float*)d_in[8];   // [3,128,128]
    const float* mb1      = (const float*)d_in[9];
    const float* mW2      = (const float*)d_in[10];  // [3,128,384]
    const float* mb2      = (const float*)d_in[11];
    const float* uU       = (const float*)d_in[12];  // [3,128,128]
    const float* uV       = (const float*)d_in[13];
    const float* uW1      = (const float*)d_in[14];  // [3,256,128]
    const float* ub1      = (const float*)d_in[15];
    const float* uW2      = (const float*)d_in[16];  // [3,128,384]
    const float* ub2      = (const float*)d_in[17];
    const float* hW1      = (const float*)d_in[18];  // [128,64]
    const float* hb1      = (const float*)d_in[19];
    const float* hW2      = (const float*)d_in[20];  // [64]
    const float* hb2      = (const float*)d_in[21];

    int N = in_sizes[0];
    int E = in_sizes[3] / 2;

    float* out   = (float*)d_out;
    float* out_v = out;                  // [N]
    float* out_p = out + N;              // [N*3]
    float* out_e = out + 4 * N;          // [2*E]
    float* out_d = out + 4 * N + 2 * E;  // [E]

    void* p;
    cudaGetSymbolAddress(&p, g_ns);    float* ns    = (float*)p;
    cudaGetSymbolAddress(&p, g_nv);    float* nv    = (float*)p;
    cudaGetSymbolAddress(&p, g_tmpH);  float* tmpH  = (float*)p;
    cudaGetSymbolAddress(&p, g_smsg);  float* smsg  = (float*)p;
    cudaGetSymbolAddress(&p, g_Uv);    float* Uv    = (float*)p;
    cudaGetSymbolAddress(&p, g_Vv);    float* Vv    = (float*)p;
    cudaGetSymbolAddress(&p, g_Vn);    float* Vn    = (float*)p;
    cudaGetSymbolAddress(&p, g_abuf);  float* abuf  = (float*)p;

    reset_kernel<<<1, 1>>>();
    edge_geom_kernel<<<(E + 255) / 256, 256>>>(pos, cell, ei, offs, out_d, out_e, E);
    init_nodes_kernel<<<(N * HID + 255) / 256, 256>>>(embed, z, N);
    cudaMemcpyAsync(out_p, pos, (size_t)N * 3 * sizeof(float), cudaMemcpyDeviceToDevice);

    for (int l = 0; l < 3; l++) {
        const float* lmfW = mfW + (size_t)l * 20 * 384;
        const float* lmfb = mfb + (size_t)l * 384;

        // s = silu(ns @ mW1 + mb1) @ mW2 + mb2
        gemm128_kernel<false, true, true><<<gemm_grid(128, N), 256>>>(
            ns, mW1 + (size_t)l * 128 * 128, mb1 + (size_t)l * 128, tmpH, N, 128, 128);
        gemm128_kernel<false, true, false><<<gemm_grid(384, N), 256>>>(
            tmpH, mW2 + (size_t)l * 128 * 384, mb2 + (size_t)l * 384, smsg, N, 128, 384);

        // edge messages read g_nvold (pre-message state, maintained by dual-write)
        edge_msg_kernel<<<256, 256>>>(lmfW, lmfb, smsg);

        // Uv = nv @ U ; Vv = nv @ V  (nv viewed as [3N,128]; fused, z selects B/C)
        {
            dim3 g(1, (3 * N + 127) / 128, 2);
            gemm_uv_kernel<<<g, 256>>>(nv,
                                       uU + (size_t)l * 128 * 128,
                                       uV + (size_t)l * 128 * 128,
                                       Uv, Vv, 3 * N);
        }

        vnorm_inner_kernel<<<(N * HID + 255) / 256, 256>>>(N);

        // hidden = silu([ns|Vn] @ uW1 + b1)   (dual-A, K=256, single pass)
        {
            dim3 g(1, (N + 127) / 128, 1);
            gemm_dualA_kernel<<<g, 256>>>(ns, Vn,
                                          uW1 + (size_t)l * 256 * 128,
                                          ub1 + (size_t)l * 128, tmpH, N);
        }
        // a = hidden @ W2 + b2
        gemm128_kernel<false, true, false><<<gemm_grid(384, N), 256>>>(
            tmpH, uW2 + (size_t)l * 128 * 384, ub2 + (size_t)l * 384, abuf, N, 128, 384);

        update_kernel<<<(N * HID + 255) / 256, 256>>>(N);
    }

    // head
    gemm128_kernel<false, true, true><<<gemm_grid(64, N), 256>>>(
        ns, hW1, hb1, tmpH, N, 128, 64);
    head2_kernel<<<(N + 255) / 256, 256>>>(hW2, hb2, out_v, N);
}